// round 7
// baseline (speedup 1.0000x reference)
#include <cuda_runtime.h>

#define NEGV   -1.0e8f
#define NBANDS 128               // 1024 rows / 8 rows per band
#define GW     1025              // boundary row: columns 0..1024
#define NSTEPS 1032              // covers last needed step s=1030

// G[b][j] = V[8b][j] over 4 states. Row 128 = final row i=1024. ~2.1 MB.
// Never initialized: every read is watermark-gated (or constant-substituted).
__device__ float4 G[(NBANDS + 1) * GW];
// PROG[b] = highest column j such that G[b][1..j] is published (release-stored).
__device__ int PROG[NBANDS + 1];

// ---------------------------------------------------------------------------
__global__ void init_kernel() {
    int i = threadIdx.x;
    if (i <= NBANDS) PROG[i] = 0;
}

// ---------------------------------------------------------------------------
__device__ __forceinline__ int ldacq(const int* p) {
    int v;
    asm volatile("ld.acquire.gpu.s32 %0, [%1];" : "=r"(v) : "l"(p) : "memory");
    return v;
}
__device__ __forceinline__ void strel(int* p, int v) {
    asm volatile("st.release.gpu.s32 [%0], %1;" :: "l"(p), "r"(v) : "memory");
}
// Plain (coherent) 16B global load — deliberately NOT __ldg/.nc: G is written
// by other CTAs during the kernel; ordering comes from the acquire above.
__device__ __forceinline__ float4 ldg4(const float4* p) {
    float4 v;
    asm volatile("ld.global.v4.f32 {%0,%1,%2,%3}, [%4];"
                 : "=f"(v.x), "=f"(v.y), "=f"(v.z), "=f"(v.w) : "l"(p) : "memory");
    return v;
}

// ---------------------------------------------------------------------------
// Persistent band DP, smem diagonal buffers (round-2-proven recurrence).
// Grid = 128 blocks x 32 threads; block b covers rows 8b+1..8b+8.
// Lane = 4*a + t : cell a (row within band), target state t (m,x,y,s).
// Cell a computes column j = s - a + 1 at step s (active for s in [a, a+1023]).
// Buffer slots: slot 0 = top halo V[8b][.], slot a+1 = cell a.
// ---------------------------------------------------------------------------
__global__ __launch_bounds__(32) void dp_kernel(const float* __restrict__ theta,
                                                const float4* __restrict__ A4) {
    __shared__ float4 D[3][10];

    const int b    = blockIdx.x;
    const int lane = threadIdx.x;
    const int a    = lane >> 2;
    const int t    = lane & 3;
    const int r    = 8 * b + a;                 // theta/A row = i-1
    const float4* Grow = G + b * GW;            // top boundary row (read; b>0)
    float*        Gout = (float*)(G + (b + 1) * GW);   // bottom row (write)

    const float4 NEG4 = make_float4(NEGV, NEGV, NEGV, NEGV);

    if (lane < 30) ((float4*)D)[lane] = NEG4;   // left halo + pre-active state
    __syncwarp();

    // A/theta register ring, depth 8: slot k holds data for step s, s&7==k.
    float4 Ar[8]; float Tr[8];
    #pragma unroll
    for (int k = 0; k < 8; ++k) {
        int col = k - a; col = col < 0 ? 0 : col;
        int idx = (r * 1024 + col) * 4 + t;
        Ar[k] = __ldg(A4 + idx);
        Tr[k] = __ldg(theta + idx);
    }

    // Halo seeding. Roles at s=0: Dn=D[0], Dm1=D[2], Dm2=D[1].
    //   D[1][0] = halo(0) = V[8b][0]; D[2][0] = halo(1) = V[8b][1].
    // hA/hB: register pipeline holding halo(s+2)/halo(s+3) at top of step s.
    int avail = 0;
    float4 hA = NEG4, hB = NEG4;
    if (lane == 0) {
        if (b == 0) {
            D[1][0] = make_float4(0.f, 0.f, 0.f, 0.f);   // THE SEED V[0][0]=0
            D[2][0] = NEG4;                              // V[0][1] = NEG
            // hA = hB = NEG (band 0's halo is NEG for all p >= 1)
        } else {
            while (avail < 3) avail = ldacq(PROG + b);
            D[1][0] = NEG4;                              // V[8b][0] = left bound
            D[2][0] = ldg4(Grow + 1);                    // halo(1)
            hA      = ldg4(Grow + 2);                    // halo(2)
            hB      = ldg4(Grow + 3);                    // halo(3)
        }
    }
    __syncwarp();

    const bool bot = (a == 7);
    const bool rel = (lane == 28);               // a=7, t=0 publishes watermark

    auto step = [&](int s, float4* Dn, float4* Dm1, float4* Dm2) {
        float4 av = Ar[s & 7];
        float  tv = Tr[s & 7];

        const float4* sp = (t == 1) ? (Dm1 + a)          // up   V[i-1][j]
                         : (t == 2) ? (Dm1 + a + 1)      // left V[i][j-1]
                                    : (Dm2 + a);         // diag V[i-1][j-1]
        float4 s4 = *sp;

        float w0 = s4.x + av.x;
        float w1 = s4.y + av.y;
        float w2 = s4.z + av.z;
        float w3 = s4.w + av.w;
        float m = fmaxf(fmaxf(w0, w1), fmaxf(w2, w3));
        float sum = __expf(w0 - m) + __expf(w1 - m) + __expf(w2 - m) + __expf(w3 - m);
        float res = m + __logf(sum) + tv;

        bool active = (s >= a) && (s <= a + 1023);
        if (active) {
            ((float*)(Dn + a + 1))[t] = res;
            if (bot) Gout[(s - 6) * 4 + t] = res;        // plain store, col j=s-6
        }

        // refill A/theta ring for step s+8 (clamped tail feeds inactive steps)
        {
            int col = s + 8 - a;
            col = col > 1023 ? 1023 : col;
            int idx = (r * 1024 + col) * 4 + t;
            Ar[s & 7] = __ldg(A4 + idx);
            Tr[s & 7] = __ldg(theta + idx);
        }

        // halo pipeline: write halo(s+2), rotate, prefetch halo(s+4)
        if (lane == 0) {
            Dn[0] = hA;                                  // halo(s+2)
            hA = hB;
            if (b != 0) {
                int p = s + 4;
                if (p <= 1024) {
                    while (avail < p) avail = ldacq(PROG + b);
                    hB = ldg4(Grow + p);
                }
            } else {
                hB = NEG4;
            }
        }
        __syncwarp();   // orders all lanes' stores before the release below
        if (rel && (s >= 7) && (s <= 1030)) strel(PROG + b + 1, s - 6);
    };

    for (int s = 0; s < NSTEPS; s += 3) {
        step(s,     D[0], D[2], D[1]);
        step(s + 1, D[1], D[0], D[2]);
        step(s + 2, D[2], D[1], D[0]);
    }
}

// ---------------------------------------------------------------------------
// Stream-ordered after dp_kernel: plain read is safe.
__global__ void final_kernel(float* out) {
    float4 v = ldg4(G + NBANDS * GW + 1024);     // V[1024][1024]
    float m = fmaxf(fmaxf(v.x, v.y), fmaxf(v.z, v.w));
    out[0] = m + __logf(__expf(v.x - m) + __expf(v.y - m) +
                        __expf(v.z - m) + __expf(v.w - m));
}

// ---------------------------------------------------------------------------
extern "C" void kernel_launch(void* const* d_in, const int* in_sizes, int n_in,
                              void* d_out, int out_size) {
    const float*  theta = (const float*)d_in[0];   // [1024,1024,4]
    const float4* A4    = (const float4*)d_in[1];  // [1024,1024,4,4]

    init_kernel<<<1, 256>>>();
    dp_kernel<<<NBANDS, 32>>>(theta, A4);
    final_kernel<<<1, 1>>>((float*)d_out);
}

// round 8
// speedup vs baseline: 7.9093x; 7.9093x over previous
#include <cuda_runtime.h>

#define NEGV   -1.0e8f
#define BH     32                // band height (rows per CTA)
#define NB     32                // number of bands
#define GW     1025              // boundary row: columns 0..1024
#define NSTEPS 1056              // 132 groups of 8; covers last step s=1054

// G[b][j] = V[32b][j] over 4 states. Row 32 = final row i=1024.
__device__ float4 G[(NB + 1) * GW];
// PROG[b] = highest column j such that G[b][1..j] is published.
__device__ int PROG[NB + 1];

// ---------------------------------------------------------------------------
__global__ void init_kernel() {
    int i = threadIdx.x;
    if (i <= NB) PROG[i] = 0;
}

// ---------------------------------------------------------------------------
__device__ __forceinline__ int ldacq(const int* p) {
    int v;
    asm volatile("ld.acquire.gpu.s32 %0, [%1];" : "=r"(v) : "l"(p) : "memory");
    return v;
}
__device__ __forceinline__ void strel(int* p, int v) {
    asm volatile("st.release.gpu.s32 [%0], %1;" :: "l"(p), "r"(v) : "memory");
}
// Plain coherent 16B global load (NOT .nc: G is written by peer CTAs).
__device__ __forceinline__ float4 ldg4(const float4* p) {
    float4 v;
    asm volatile("ld.global.v4.f32 {%0,%1,%2,%3}, [%4];"
                 : "=f"(v.x), "=f"(v.y), "=f"(v.z), "=f"(v.w) : "l"(p) : "memory");
    return v;
}

// ---------------------------------------------------------------------------
// Persistent band DP, smem diagonal buffers. Grid = 32 blocks x 128 threads;
// block b covers rows 32b+1..32b+32. Thread = 4*a + t : cell a (row in band),
// target state t. Cell a computes column j = s - a + 1 at step s
// (active for s in [a, a+1023]). Buffer slot 0 = top halo, slot a+1 = cell a.
//   up   (t=1): Dm1[a]     left (t=2): Dm1[a+1]     diag (t=0,3): Dm2[a]
// ---------------------------------------------------------------------------
__global__ __launch_bounds__(128) void dp_kernel(const float* __restrict__ theta,
                                                 const float4* __restrict__ A4) {
    __shared__ float4 D[3][BH + 2];

    const int b   = blockIdx.x;
    const int tid = threadIdx.x;
    const int a   = tid >> 2;
    const int t   = tid & 3;
    const int r   = BH * b + a;                 // theta/A row = i-1
    const float4* Grow = G + b * GW;            // top boundary row (read; b>0)
    float*        Gout = (float*)(G + (b + 1) * GW);   // bottom row (write)

    const float4 NEG4 = make_float4(NEGV, NEGV, NEGV, NEGV);

    if (tid < 3 * (BH + 2)) ((float4*)D)[tid] = NEG4;   // halos + pre-active
    __syncthreads();

    // A/theta register ring, depth 8: slot k holds data for step s, s&7==k.
    float4 Ar[8]; float Tr[8];
    #pragma unroll
    for (int k = 0; k < 8; ++k) {
        int col = k - a; col = col < 0 ? 0 : col;
        int idx = (r * 1024 + col) * 4 + t;
        Ar[k] = __ldg(A4 + idx);
        Tr[k] = __ldg(theta + idx);
    }

    // Seed. Roles at s=0: Dn=D[0], Dm1=D[2], Dm2=D[1].
    //   D[1][0] = halo(0) = V[32b][0]; D[2][0] = halo(1) = V[32b][1].
    int avail = 0;
    if (tid == 0) {
        if (b == 0) {
            D[1][0] = make_float4(0.f, 0.f, 0.f, 0.f);   // THE SEED V[0][0]=0
            D[2][0] = NEG4;                              // V[0][1] = NEG
        } else {
            while (avail < 1) avail = ldacq(PROG + b);
            D[1][0] = NEG4;                              // V[32b][0] left bound
            D[2][0] = ldg4(Grow + 1);
        }
    }
    __syncthreads();

    const bool bot = (a == BH - 1);

    float4* Pn  = D[0];
    float4* Pm1 = D[2];
    float4* Pm2 = D[1];

    for (int s0 = 0; s0 < NSTEPS; s0 += 8) {
        // Group prologue: fetch halo(s0+2 .. s0+9) into registers (tid 0).
        float4 h[8];
        if (tid == 0) {
            if (b == 0 || s0 + 2 > 1024) {
                #pragma unroll
                for (int k = 0; k < 8; ++k) h[k] = NEG4;
            } else {
                int need = s0 + 9; need = need > 1024 ? 1024 : need;
                while (avail < need) avail = ldacq(PROG + b);
                #pragma unroll
                for (int k = 0; k < 8; ++k) {
                    int p = s0 + 2 + k; p = p > 1024 ? 1024 : p;
                    h[k] = ldg4(Grow + p);
                }
            }
        }

        #pragma unroll
        for (int k = 0; k < 8; ++k) {
            const int s = s0 + k;
            float4 av = Ar[k];
            float  tv = Tr[k];

            const float4* sp = (t == 1) ? (Pm1 + a)        // up   V[i-1][j]
                             : (t == 2) ? (Pm1 + a + 1)    // left V[i][j-1]
                                        : (Pm2 + a);       // diag V[i-1][j-1]
            float4 s4 = *sp;

            float w0 = s4.x + av.x;
            float w1 = s4.y + av.y;
            float w2 = s4.z + av.z;
            float w3 = s4.w + av.w;
            float m = fmaxf(fmaxf(w0, w1), fmaxf(w2, w3));
            float sum = __expf(w0 - m) + __expf(w1 - m) +
                        __expf(w2 - m) + __expf(w3 - m);
            float res = m + __logf(sum) + tv;

            bool active = (s >= a) && (s <= a + 1023);
            if (active) {
                ((float*)(Pn + a + 1))[t] = res;
                if (bot) Gout[(s - (BH - 2)) * 4 + t] = res;   // col j = s-30
            }

            // refill ring for step s+8
            {
                int col = s + 8 - a;
                col = col < 0 ? 0 : (col > 1023 ? 1023 : col);
                int idx = (r * 1024 + col) * 4 + t;
                Ar[k] = __ldg(A4 + idx);
                Tr[k] = __ldg(theta + idx);
            }

            if (tid == 0) Pn[0] = h[k];        // halo(s+2) for next step's Dm1[0]
            __syncthreads();

            float4* tmp = Pm2; Pm2 = Pm1; Pm1 = Pn; Pn = tmp;
        }

        // One release per group: columns up to jmax are now globally ordered
        // behind the last __syncthreads (block causality -> gpu release).
        if (tid == 4 * (BH - 1)) {
            int jmax = s0 + 7 - (BH - 2);
            if (jmax >= 1) strel(PROG + b + 1, jmax > 1024 ? 1024 : jmax);
        }
    }
}

// ---------------------------------------------------------------------------
// Stream-ordered after dp_kernel: plain read is safe.
__global__ void final_kernel(float* out) {
    float4 v = ldg4(G + NB * GW + 1024);       // V[1024][1024]
    float m = fmaxf(fmaxf(v.x, v.y), fmaxf(v.z, v.w));
    out[0] = m + __logf(__expf(v.x - m) + __expf(v.y - m) +
                        __expf(v.z - m) + __expf(v.w - m));
}

// ---------------------------------------------------------------------------
extern "C" void kernel_launch(void* const* d_in, const int* in_sizes, int n_in,
                              void* d_out, int out_size) {
    const float*  theta = (const float*)d_in[0];   // [1024,1024,4]
    const float4* A4    = (const float4*)d_in[1];  // [1024,1024,4,4]

    init_kernel<<<1, 64>>>();
    dp_kernel<<<NB, 128>>>(theta, A4);
    final_kernel<<<1, 1>>>((float*)d_out);
}